// round 16
// baseline (speedup 1.0000x reference)
#include <cuda_runtime.h>
#include <cstdint>
#include <cstddef>

#define BM 128
#define BN 128
#define BK 32
#define STAGES 3
// panel layout: per k8 slice a contiguous [BM rows x 8 words] panel (1024 words)
// stage = A(4 panels) + B(4 panels) = 8192 words = 32 KB, no padding
#define PANEL_W   1024
#define MAT_WORDS 4096
#define STAGE_WORDS 8192
#define GEMM_SMEM (STAGES * STAGE_WORDS * 4)   // 98304 B -> 2 CTAs/SM

// ---------------- scratch (allocation-free rule: __device__ globals) ----------------
static __device__ float g_qkv [(size_t)16384 * 3072];   // 201 MB
static __device__ float g_attn[(size_t)16384 * 1024];   //  67 MB (k-permuted tf32)
static __device__ float g_xr  [(size_t)16384 * 1024];   //  64 MB (k-permuted tf32 x)
static __device__ float g_wqkv[(size_t)3072  * 1024];   //  12 MB (k-permuted tf32 Wqkv)
static __device__ float g_wo  [(size_t)1024  * 1024];   //   4 MB (k-permuted tf32 Wo)

__device__ __forceinline__ unsigned f2tf(float f) {
    unsigned u;
    asm("cvt.rna.tf32.f32 %0, %1;" : "=r"(u) : "f"(f));
    return u;
}

__device__ __forceinline__ uint32_t smem_u32(const void* p) {
    uint32_t a;
    asm("{ .reg .u64 t; cvta.to.shared.u64 t, %1; cvt.u32.u64 %0, t; }"
        : "=r"(a) : "l"(p));
    return a;
}

__device__ __forceinline__ void mma_tf32(float c[4], const unsigned a[4], const unsigned b[2]) {
    asm volatile(
        "mma.sync.aligned.m16n8k8.row.col.f32.tf32.tf32.f32 "
        "{%0,%1,%2,%3}, {%4,%5,%6,%7}, {%8,%9}, {%0,%1,%2,%3};\n"
        : "+f"(c[0]), "+f"(c[1]), "+f"(c[2]), "+f"(c[3])
        : "r"(a[0]), "r"(a[1]), "r"(a[2]), "r"(a[3]), "r"(b[0]), "r"(b[1]));
}

// ---------------- tf32 pre-rounding + k8 interleave pass ----------------
// per 8-group along last dim, stored order = [k0,k4,k1,k5,k2,k6,k3,k7]
// so mma fragment cols (c, c+4) become one contiguous 8-byte pair.
__global__ void __launch_bounds__(256)
round_perm_tf32(const float* __restrict__ in, float* __restrict__ out, int n8)
{
    int i = blockIdx.x * blockDim.x + threadIdx.x;
    const int stride = gridDim.x * blockDim.x;
    const float4* src = (const float4*)in;
    float4* dst = (float4*)out;
    for (; i < n8; i += stride) {
        float4 v0 = src[2 * i];       // k0..k3
        float4 v1 = src[2 * i + 1];   // k4..k7
        float4 w0, w1;
        w0.x = __uint_as_float(f2tf(v0.x));  // k0
        w0.y = __uint_as_float(f2tf(v1.x));  // k4
        w0.z = __uint_as_float(f2tf(v0.y));  // k1
        w0.w = __uint_as_float(f2tf(v1.y));  // k5
        w1.x = __uint_as_float(f2tf(v0.z));  // k2
        w1.y = __uint_as_float(f2tf(v1.z));  // k6
        w1.z = __uint_as_float(f2tf(v0.w));  // k3
        w1.w = __uint_as_float(f2tf(v1.w));  // k7
        dst[2 * i]     = w0;
        dst[2 * i + 1] = w1;
    }
}

// ---------------- tf32 NT-GEMM: 256 thr, 8 warps 64x32, BK=32, panel smem, LDS.64 frags ----------------
// C[m,n] = sum_k A[m,k]*B[n,k] (+bias[n]); A,B tf32-rounded AND k8-permuted, row-major.
template <bool HAS_BIAS>
__global__ void __launch_bounds__(256, 2)
gemm_tf32_cp(const float* __restrict__ A, const float* __restrict__ Bm,
             const float* __restrict__ bias, float* __restrict__ C,
             int M, int Nd, int K)
{
    extern __shared__ __align__(16) unsigned sm[];
    const uint32_t sbase = smem_u32(sm);

    const int tid  = threadIdx.x;
    const int warp = tid >> 5;
    const int lane = tid & 31;
    const int g    = lane >> 2;   // 0..7
    const int c    = lane & 3;    // 0..3

    const int bm0 = blockIdx.y * BM;
    const int bn0 = blockIdx.x * BN;

    const int wm = (warp >> 2) * 64;   // 2x4 warp raster, 64x32 warp tile
    const int wn = (warp &  3) * 32;

    // producer mapping: q = 16B quad (perm slots 4q..4q+3), rows r0+32i
    const int q  = tid & 7;       // 0..7
    const int r0 = tid >> 3;      // 0..31
    const float* Ag = A  + (size_t)(bm0 + r0) * K + q * 4;
    const float* Bg = Bm + (size_t)(bn0 + r0) * K + q * 4;

    float acc[4][4][4];
    #pragma unroll
    for (int i = 0; i < 4; i++)
        #pragma unroll
        for (int j = 0; j < 4; j++)
            #pragma unroll
            for (int r = 0; r < 4; r++) acc[i][j][r] = 0.f;

    const int nChunks = K / BK;   // 32

    // smem dst (stage 0): panel = q>>1, within-panel 16B half = q&1
    uint32_t dA[4];
    #pragma unroll
    for (int i = 0; i < 4; i++)
        dA[i] = sbase + (uint32_t)((((q >> 1) * PANEL_W) + (r0 + 32 * i) * 8 + (q & 1) * 4) * 4);

    // ---- prologue: stages 0..STAGES-2 ----
    #pragma unroll
    for (int s = 0; s < STAGES - 1; s++) {
        const uint32_t so = (uint32_t)(s * STAGE_WORDS * 4);
        #pragma unroll
        for (int i = 0; i < 4; i++) {
            const float* ga = Ag + (size_t)(32 * i) * K + s * BK;
            const float* gb = Bg + (size_t)(32 * i) * K + s * BK;
            asm volatile("cp.async.cg.shared.global [%0], [%1], 16;" :: "r"(dA[i] + so), "l"(ga));
            asm volatile("cp.async.cg.shared.global [%0], [%1], 16;" :: "r"(dA[i] + so + MAT_WORDS * 4), "l"(gb));
        }
        asm volatile("cp.async.commit_group;");
    }

    for (int it = 0; it < nChunks; ++it) {
        asm volatile("cp.async.wait_group %0;" :: "n"(STAGES - 2));
        __syncthreads();

        // issue stage for chunk it+STAGES-1 (stage consumed at iter it-1; barrier above protects it)
        const int kc = it + STAGES - 1;
        if (kc < nChunks) {
            const uint32_t so = (uint32_t)((kc % STAGES) * STAGE_WORDS * 4);
            #pragma unroll
            for (int i = 0; i < 4; i++) {
                const float* ga = Ag + (size_t)(32 * i) * K + kc * BK;
                const float* gb = Bg + (size_t)(32 * i) * K + kc * BK;
                asm volatile("cp.async.cg.shared.global [%0], [%1], 16;" :: "r"(dA[i] + so), "l"(ga));
                asm volatile("cp.async.cg.shared.global [%0], [%1], 16;" :: "r"(dA[i] + so + MAT_WORDS * 4), "l"(gb));
            }
        }
        asm volatile("cp.async.commit_group;");

        // compute on stage it%STAGES : 4 k8-steps (one panel each), LDS.64 fragment loads
        const unsigned* __restrict__ Acur = sm + (it % STAGES) * STAGE_WORDS;
        const unsigned* __restrict__ Bcur = Acur + MAT_WORDS;

        #pragma unroll
        for (int ks = 0; ks < 4; ks++) {
            const unsigned* Ap = Acur + ks * PANEL_W;
            const unsigned* Bp = Bcur + ks * PANEL_W;
            unsigned af[4][4];
            #pragma unroll
            for (int i = 0; i < 4; i++) {
                const int base = (wm + i * 16 + g) * 8 + 2 * c;
                const uint2 p0 = *(const uint2*)(Ap + base);        // a0 (k=c), a2 (k=c+4)
                const uint2 p1 = *(const uint2*)(Ap + base + 64);   // a1, a3 (row+8)
                af[i][0] = p0.x; af[i][1] = p1.x; af[i][2] = p0.y; af[i][3] = p1.y;
            }
            unsigned bf[4][2];
            #pragma unroll
            for (int j = 0; j < 4; j++) {
                const int base = (wn + j * 8 + g) * 8 + 2 * c;
                const uint2 p = *(const uint2*)(Bp + base);         // b0 (k=c), b1 (k=c+4)
                bf[j][0] = p.x; bf[j][1] = p.y;
            }
            #pragma unroll
            for (int i = 0; i < 4; i++)
                #pragma unroll
                for (int j = 0; j < 4; j++)
                    mma_tf32(acc[i][j], af[i], bf[j]);
        }
    }

    // ---- epilogue (output dims unpermuted) ----
    #pragma unroll
    for (int i = 0; i < 4; i++) {
        const int row = bm0 + wm + i * 16 + g;
        #pragma unroll
        for (int j = 0; j < 4; j++) {
            const int col = bn0 + wn + j * 8 + c * 2;
            float2 add = make_float2(0.f, 0.f);
            if (HAS_BIAS) add = *(const float2*)(bias + col);
            float2 v0 = make_float2(acc[i][j][0] + add.x, acc[i][j][1] + add.y);
            float2 v1 = make_float2(acc[i][j][2] + add.x, acc[i][j][3] + add.y);
            *(float2*)(C + (size_t)row       * Nd + col) = v0;
            *(float2*)(C + (size_t)(row + 8) * Nd + col) = v1;
        }
    }
}

// ---------------- per-position cross-head attention ----------------
// stores output tf32-rounded AND k8-permuted (it is the O-projection's contraction input)
__global__ void __launch_bounds__(128)
attn_kernel(const float* __restrict__ qkv, float* __restrict__ attn)
{
    __shared__ float s[3072];
    __shared__ float sS[16 * 17];
    __shared__ float sW[16 * 17];

    const int tid = threadIdx.x;
    const size_t m = blockIdx.x;

    const float4* src = (const float4*)(qkv + m * 3072);
    float4* dst = (float4*)s;
    #pragma unroll
    for (int i = 0; i < 6; i++) dst[tid + i * 128] = src[tid + i * 128];
    __syncthreads();

    const float* q = s;
    const float* k = s + 1024;
    const float* v = s + 2048;

    #pragma unroll
    for (int e = 0; e < 2; e++) {
        const int idx = tid + e * 128;
        const int h  = idx >> 4;
        const int gg = idx & 15;
        float sum = 0.f;
        #pragma unroll
        for (int d = 0; d < 64; d++) {
            const int dd = (d + gg) & 63;   // rotation kills stride-64 bank conflicts
            sum += q[h * 64 + dd] * k[gg * 64 + dd];
        }
        sS[h * 17 + gg] = sum * 0.03125f;   // 1/sqrt(1024)
    }
    __syncthreads();

    if (tid < 16) {
        float mx = -1e30f;
        #pragma unroll
        for (int j = 0; j < 16; j++) mx = fmaxf(mx, sS[tid * 17 + j]);
        float w[16], sum = 0.f;
        #pragma unroll
        for (int j = 0; j < 16; j++) { w[j] = __expf(sS[tid * 17 + j] - mx); sum += w[j]; }
        const float inv = 1.f / sum;
        #pragma unroll
        for (int j = 0; j < 16; j++) sW[tid * 17 + j] = w[j] * inv;
    }
    __syncthreads();

    const int h  = tid >> 3;
    const int d0 = (tid & 7) * 8;   // 8-aligned -> exactly one k8 perm group
    float out[8];
    #pragma unroll
    for (int j = 0; j < 8; j++) out[j] = 0.f;
    #pragma unroll
    for (int gg = 0; gg < 16; gg++) {
        const float w = sW[h * 17 + gg];
        #pragma unroll
        for (int j = 0; j < 8; j++) out[j] += w * v[gg * 64 + d0 + j];
    }
    // permuted store: slots [k0,k4,k1,k5 | k2,k6,k3,k7], tf32-rounded
    float4* o4 = (float4*)(attn + m * 1024 + h * 64 + d0);
    o4[0] = make_float4(__uint_as_float(f2tf(out[0])), __uint_as_float(f2tf(out[4])),
                        __uint_as_float(f2tf(out[1])), __uint_as_float(f2tf(out[5])));
    o4[1] = make_float4(__uint_as_float(f2tf(out[2])), __uint_as_float(f2tf(out[6])),
                        __uint_as_float(f2tf(out[3])), __uint_as_float(f2tf(out[7])));
}

// ---------------- launch ----------------
extern "C" void kernel_launch(void* const* d_in, const int* in_sizes, int n_in,
                              void* d_out, int out_size)
{
    const float* x    = (const float*)d_in[0];   // (4,4096,1024)
    const float* Wqkv = (const float*)d_in[1];   // (3072,1024)
    const float* Wo   = (const float*)d_in[2];   // (1024,1024)
    const float* bo   = (const float*)d_in[3];   // (1024)
    float* out = (float*)d_out;

    float *qkv = nullptr, *attn = nullptr, *xr = nullptr, *wqkvr = nullptr, *wor = nullptr;
    cudaGetSymbolAddress((void**)&qkv,   g_qkv);
    cudaGetSymbolAddress((void**)&attn,  g_attn);
    cudaGetSymbolAddress((void**)&xr,    g_xr);
    cudaGetSymbolAddress((void**)&wqkvr, g_wqkv);
    cudaGetSymbolAddress((void**)&wor,   g_wo);

    cudaFuncSetAttribute(gemm_tf32_cp<false>, cudaFuncAttributeMaxDynamicSharedMemorySize, GEMM_SMEM);
    cudaFuncSetAttribute(gemm_tf32_cp<true >, cudaFuncAttributeMaxDynamicSharedMemorySize, GEMM_SMEM);

    const int M = 16384, K = 1024;

    // tf32 pre-rounding + k8 interleave (HBM-streaming)
    round_perm_tf32<<<4096, 256>>>(x,    xr,    (16384 * 1024) / 8);
    round_perm_tf32<<<1536, 256>>>(Wqkv, wqkvr, (3072  * 1024) / 8);
    round_perm_tf32<<<512,  256>>>(Wo,   wor,   (1024  * 1024) / 8);

    gemm_tf32_cp<false><<<dim3(3072 / BN, M / BM), 256, GEMM_SMEM>>>(xr,   wqkvr, nullptr, qkv, M, 3072, K);
    attn_kernel<<<M, 128>>>(qkv, attn);
    gemm_tf32_cp<true ><<<dim3(1024 / BN, M / BM), 256, GEMM_SMEM>>>(attn, wor,   bo,      out, M, 1024, K);
}

// round 17
// speedup vs baseline: 1.5471x; 1.5471x over previous
#include <cuda_runtime.h>
#include <cuda.h>
#include <cstdint>
#include <cstddef>

#define BM 128
#define BN 128
#define BK 32
#define STAGES 3
#define STAGE_BYTES 32768                 // A 16KB + B 16KB, SW128-swizzled tiles
#define STAGE_WORDS (STAGE_BYTES / 4)
#define GEMM_SMEM (STAGES * STAGE_BYTES + 1024)   // + alignment slack -> 2 CTAs/SM

// ---------------- scratch (allocation-free rule: __device__ globals) ----------------
static __device__ float g_qkv [(size_t)16384 * 3072];   // 201 MB
static __device__ float g_attn[(size_t)16384 * 1024];   //  67 MB (tf32-rounded)
static __device__ float g_xr  [(size_t)16384 * 1024];   //  64 MB (tf32-rounded x)
static __device__ float g_wqkv[(size_t)3072  * 1024];   //  12 MB (tf32-rounded Wqkv)
static __device__ float g_wo  [(size_t)1024  * 1024];   //   4 MB (tf32-rounded Wo)

__device__ __forceinline__ unsigned f2tf(float f) {
    unsigned u;
    asm("cvt.rna.tf32.f32 %0, %1;" : "=r"(u) : "f"(f));
    return u;
}

__device__ __forceinline__ uint32_t smem_u32(const void* p) {
    uint32_t a;
    asm("{ .reg .u64 t; cvta.to.shared.u64 t, %1; cvt.u32.u64 %0, t; }"
        : "=r"(a) : "l"(p));
    return a;
}

__device__ __forceinline__ void mma_tf32(float c[4], const unsigned a[4], const unsigned b[2]) {
    asm volatile(
        "mma.sync.aligned.m16n8k8.row.col.f32.tf32.tf32.f32 "
        "{%0,%1,%2,%3}, {%4,%5,%6,%7}, {%8,%9}, {%0,%1,%2,%3};\n"
        : "+f"(c[0]), "+f"(c[1]), "+f"(c[2]), "+f"(c[3])
        : "r"(a[0]), "r"(a[1]), "r"(a[2]), "r"(a[3]), "r"(b[0]), "r"(b[1]));
}

#define MBARRIER_INIT(addr, cnt) \
    asm volatile("mbarrier.init.shared.b64 [%0], %1;" :: "r"((uint32_t)(addr)), "r"((uint32_t)(cnt)) : "memory")

#define MBARRIER_EXPECT_TX(addr, bytes) \
    asm volatile("mbarrier.arrive.expect_tx.shared.b64 _, [%0], %1;" :: "r"((uint32_t)(addr)), "r"((uint32_t)(bytes)) : "memory")

#define MBARRIER_WAIT_PARITY(mbar_smem_addr, phase_parity) do { \
    uint32_t _mbar = (uint32_t)(mbar_smem_addr); \
    uint32_t _parity = (uint32_t)(phase_parity); \
    uint32_t _done; \
    asm volatile( \
        "{\n\t.reg .pred p;\n\t" \
        "mbarrier.try_wait.parity.acquire.cta.shared::cta.b64 p, [%1], %2;\n\t" \
        "selp.b32 %0, 1, 0, p;\n\t}" \
        : "=r"(_done) : "r"(_mbar), "r"(_parity) : "memory"); \
    if (!_done) { \
        asm volatile( \
            "{\n\t.reg .pred P1;\n\t" \
            "WAIT_LOOP_%=:\n\t" \
            "mbarrier.try_wait.parity.acquire.cta.shared::cta.b64 P1, [%0], %1, 0x989680;\n\t" \
            "@P1 bra.uni WAIT_DONE_%=;\n\t" \
            "bra.uni WAIT_LOOP_%=;\n\t" \
            "WAIT_DONE_%=:\n\t}" \
            :: "r"(_mbar), "r"(_parity) : "memory"); \
    } \
} while(0)

#define TMA_LOAD_2D(dst, map, x, y, mbar) \
    asm volatile("cp.async.bulk.tensor.2d.shared::cta.global.tile.mbarrier::complete_tx::bytes " \
                 "[%0], [%1, {%2, %3}], [%4];" \
                 :: "r"((uint32_t)(dst)), "l"(map), "r"((int)(x)), "r"((int)(y)), "r"((uint32_t)(mbar)) : "memory")

// ---------------- tf32 pre-rounding pass ----------------
__global__ void __launch_bounds__(256)
round_tf32(const float* __restrict__ in, float* __restrict__ out, int n4)
{
    int i = blockIdx.x * blockDim.x + threadIdx.x;
    const int stride = gridDim.x * blockDim.x;
    const float4* src = (const float4*)in;
    float4* dst = (float4*)out;
    for (; i < n4; i += stride) {
        float4 v = src[i];
        v.x = __uint_as_float(f2tf(v.x));
        v.y = __uint_as_float(f2tf(v.y));
        v.z = __uint_as_float(f2tf(v.z));
        v.w = __uint_as_float(f2tf(v.w));
        dst[i] = v;
    }
}

// ---------------- tf32 NT-GEMM: TMA producer, 4 warps 64x64, BK=32, 3-stage mbarrier pipe ----------------
// C[m,n] = sum_k A[m,k]*B[n,k] (+bias[n]); A,B tf32-rounded fp32, row-major, K contiguous.
// TMA tiles arrive SW128-swizzled: elem (row, kcol) at byte  row*128 + ((kcol*4) ^ ((row&7)<<4)).
template <bool HAS_BIAS>
__global__ void __launch_bounds__(128, 2)
gemm_tma(const __grid_constant__ CUtensorMap tmA, const __grid_constant__ CUtensorMap tmB,
         const float* __restrict__ bias, float* __restrict__ C, int Nd, int K)
{
    extern __shared__ unsigned sm[];
    __shared__ __align__(8) uint64_t mbar_s[STAGES];

    const uint32_t rawBase = smem_u32(sm);
    const uint32_t alignW  = ((1024u - (rawBase & 1023u)) & 1023u) >> 2;   // word offset to 1024B-aligned
    const uint32_t tileB0  = rawBase + alignW * 4;                          // byte addr of stage 0

    const int tid  = threadIdx.x;
    const int warp = tid >> 5;
    const int lane = tid & 31;
    const int g    = lane >> 2;   // 0..7
    const int c    = lane & 3;    // 0..3

    const int bm0 = blockIdx.y * BM;
    const int bn0 = blockIdx.x * BN;

    const int wm = (warp >> 1) * 64;   // 2x2 warp raster, 64x64 warp tile
    const int wn = (warp &  1) * 64;

    uint32_t mb[STAGES];
    #pragma unroll
    for (int s = 0; s < STAGES; s++) mb[s] = smem_u32(&mbar_s[s]);

    if (tid == 0) {
        #pragma unroll
        for (int s = 0; s < STAGES; s++) MBARRIER_INIT(mb[s], 1);
    }
    __syncthreads();

    const int nChunks = K / BK;   // 32

    // ---- prologue: issue stages 0..STAGES-2 ----
    if (tid == 0) {
        #pragma unroll
        for (int s = 0; s < STAGES - 1; s++) {
            MBARRIER_EXPECT_TX(mb[s], STAGE_BYTES);
            TMA_LOAD_2D(tileB0 + s * STAGE_BYTES,         &tmA, s * BK, bm0, mb[s]);
            TMA_LOAD_2D(tileB0 + s * STAGE_BYTES + 16384, &tmB, s * BK, bn0, mb[s]);
        }
    }

    float acc[4][8][4];
    #pragma unroll
    for (int i = 0; i < 4; i++)
        #pragma unroll
        for (int j = 0; j < 8; j++)
            #pragma unroll
            for (int r = 0; r < 4; r++) acc[i][j][r] = 0.f;

    // warp-uniform swizzle key: all fragment rows are == g (mod 8)  ->  key = 4g (words)
    const int kw = g * 4;

    for (int it = 0; it < nChunks; ++it) {
        const int s = it % STAGES;
        MBARRIER_WAIT_PARITY(mb[s], (it / STAGES) & 1);
        __syncthreads();   // all warps done with stage (it+2)%3 (consumed at it-1) -> safe to refill

        const int kc = it + STAGES - 1;
        if (kc < nChunks && tid == 0) {
            const int s2 = kc % STAGES;
            MBARRIER_EXPECT_TX(mb[s2], STAGE_BYTES);
            TMA_LOAD_2D(tileB0 + s2 * STAGE_BYTES,         &tmA, kc * BK, bm0, mb[s2]);
            TMA_LOAD_2D(tileB0 + s2 * STAGE_BYTES + 16384, &tmB, kc * BK, bn0, mb[s2]);
        }

        // compute on stage s, word-indexed off sm[] (keeps shared address space)
        const uint32_t aW = alignW + (uint32_t)s * STAGE_WORDS + (uint32_t)(wm * 32 + g * 32);
        const uint32_t bW = alignW + (uint32_t)s * STAGE_WORDS + 4096u + (uint32_t)(wn * 32 + g * 32);

        unsigned af[2][4][4], bf[2][8][2];

        // load k8-step 0 into buf 0
        {
            const int cx0 = (c)     ^ kw;
            const int cx1 = (c + 4) ^ kw;
            #pragma unroll
            for (int i = 0; i < 4; i++) {
                const uint32_t base = aW + i * 512;
                af[0][i][0] = sm[base + cx0];
                af[0][i][1] = sm[base + 256 + cx0];
                af[0][i][2] = sm[base + cx1];
                af[0][i][3] = sm[base + 256 + cx1];
            }
            #pragma unroll
            for (int j = 0; j < 8; j++) {
                const uint32_t base = bW + j * 256;
                bf[0][j][0] = sm[base + cx0];
                bf[0][j][1] = sm[base + cx1];
            }
        }

        #pragma unroll
        for (int ks = 0; ks < 4; ks++) {
            const int cur = ks & 1;
            if (ks < 3) {               // prefetch next k8-step into other buffer
                const int cx0 = ((ks + 1) * 8 + c)     ^ kw;
                const int cx1 = ((ks + 1) * 8 + c + 4) ^ kw;
                #pragma unroll
                for (int i = 0; i < 4; i++) {
                    const uint32_t base = aW + i * 512;
                    af[cur ^ 1][i][0] = sm[base + cx0];
                    af[cur ^ 1][i][1] = sm[base + 256 + cx0];
                    af[cur ^ 1][i][2] = sm[base + cx1];
                    af[cur ^ 1][i][3] = sm[base + 256 + cx1];
                }
                #pragma unroll
                for (int j = 0; j < 8; j++) {
                    const uint32_t base = bW + j * 256;
                    bf[cur ^ 1][j][0] = sm[base + cx0];
                    bf[cur ^ 1][j][1] = sm[base + cx1];
                }
            }
            #pragma unroll
            for (int i = 0; i < 4; i++)
                #pragma unroll
                for (int j = 0; j < 8; j++)
                    mma_tf32(acc[i][j], af[cur][i], bf[cur][j]);
        }
    }

    // ---- epilogue ----
    #pragma unroll
    for (int i = 0; i < 4; i++) {
        const int row = bm0 + wm + i * 16 + g;
        #pragma unroll
        for (int j = 0; j < 8; j++) {
            const int col = bn0 + wn + j * 8 + c * 2;
            float2 add = make_float2(0.f, 0.f);
            if (HAS_BIAS) add = *(const float2*)(bias + col);
            float2 v0 = make_float2(acc[i][j][0] + add.x, acc[i][j][1] + add.y);
            float2 v1 = make_float2(acc[i][j][2] + add.x, acc[i][j][3] + add.y);
            *(float2*)(C + (size_t)row       * Nd + col) = v0;
            *(float2*)(C + (size_t)(row + 8) * Nd + col) = v1;
        }
    }
}

// ---------------- per-position cross-head attention ----------------
__global__ void __launch_bounds__(128)
attn_kernel(const float* __restrict__ qkv, float* __restrict__ attn)
{
    __shared__ float s[3072];
    __shared__ float sS[16 * 17];
    __shared__ float sW[16 * 17];

    const int tid = threadIdx.x;
    const size_t m = blockIdx.x;

    const float4* src = (const float4*)(qkv + m * 3072);
    float4* dst = (float4*)s;
    #pragma unroll
    for (int i = 0; i < 6; i++) dst[tid + i * 128] = src[tid + i * 128];
    __syncthreads();

    const float* q = s;
    const float* k = s + 1024;
    const float* v = s + 2048;

    #pragma unroll
    for (int e = 0; e < 2; e++) {
        const int idx = tid + e * 128;
        const int h  = idx >> 4;
        const int gg = idx & 15;
        float sum = 0.f;
        #pragma unroll
        for (int d = 0; d < 64; d++) {
            const int dd = (d + gg) & 63;   // rotation kills stride-64 bank conflicts
            sum += q[h * 64 + dd] * k[gg * 64 + dd];
        }
        sS[h * 17 + gg] = sum * 0.03125f;   // 1/sqrt(1024)
    }
    __syncthreads();

    if (tid < 16) {
        float mx = -1e30f;
        #pragma unroll
        for (int j = 0; j < 16; j++) mx = fmaxf(mx, sS[tid * 17 + j]);
        float w[16], sum = 0.f;
        #pragma unroll
        for (int j = 0; j < 16; j++) { w[j] = __expf(sS[tid * 17 + j] - mx); sum += w[j]; }
        const float inv = 1.f / sum;
        #pragma unroll
        for (int j = 0; j < 16; j++) sW[tid * 17 + j] = w[j] * inv;
    }
    __syncthreads();

    const int h  = tid >> 3;
    const int d0 = (tid & 7) * 8;
    float out[8];
    #pragma unroll
    for (int j = 0; j < 8; j++) out[j] = 0.f;
    #pragma unroll
    for (int gg = 0; gg < 16; gg++) {
        const float w = sW[h * 17 + gg];
        #pragma unroll
        for (int j = 0; j < 8; j++) out[j] += w * v[gg * 64 + d0 + j];
    }
    float4* o4 = (float4*)(attn + m * 1024 + h * 64 + d0);
    o4[0] = make_float4(__uint_as_float(f2tf(out[0])), __uint_as_float(f2tf(out[1])),
                        __uint_as_float(f2tf(out[2])), __uint_as_float(f2tf(out[3])));
    o4[1] = make_float4(__uint_as_float(f2tf(out[4])), __uint_as_float(f2tf(out[5])),
                        __uint_as_float(f2tf(out[6])), __uint_as_float(f2tf(out[7])));
}

// ---------------- host: tensormap encode via driver entry point (cudart-only) ----------------
typedef CUresult (*TmEncodeFn)(CUtensorMap*, CUtensorMapDataType, cuuint32_t, void*,
                               const cuuint64_t*, const cuuint64_t*, const cuuint32_t*,
                               const cuuint32_t*, CUtensorMapInterleave, CUtensorMapSwizzle,
                               CUtensorMapL2promotion, CUtensorMapFloatOOBfill);

static void encode_map(TmEncodeFn fn, CUtensorMap* tm, void* base, uint64_t rows, uint64_t cols)
{
    cuuint64_t dims[2]    = {cols, rows};          // dim0 = K (contiguous), dim1 = rows
    cuuint64_t strides[1] = {cols * sizeof(float)};
    cuuint32_t box[2]     = {BK, BM};              // 32 cols (128B) x 128 rows
    cuuint32_t estr[2]    = {1, 1};
    fn(tm, CU_TENSOR_MAP_DATA_TYPE_FLOAT32, 2, base, dims, strides, box, estr,
       CU_TENSOR_MAP_INTERLEAVE_NONE, CU_TENSOR_MAP_SWIZZLE_128B,
       CU_TENSOR_MAP_L2_PROMOTION_L2_128B, CU_TENSOR_MAP_FLOAT_OOB_FILL_NONE);
}

extern "C" void kernel_launch(void* const* d_in, const int* in_sizes, int n_in,
                              void* d_out, int out_size)
{
    const float* x    = (const float*)d_in[0];   // (4,4096,1024)
    const float* Wqkv = (const float*)d_in[1];   // (3072,1024)
    const float* Wo   = (const float*)d_in[2];   // (1024,1024)
    const float* bo   = (const float*)d_in[3];   // (1024)
    float* out = (float*)d_out;

    float *qkv = nullptr, *attn = nullptr, *xr = nullptr, *wqkvr = nullptr, *wor = nullptr;
    cudaGetSymbolAddress((void**)&qkv,   g_qkv);
    cudaGetSymbolAddress((void**)&attn,  g_attn);
    cudaGetSymbolAddress((void**)&xr,    g_xr);
    cudaGetSymbolAddress((void**)&wqkvr, g_wqkv);
    cudaGetSymbolAddress((void**)&wor,   g_wo);

    TmEncodeFn enc = nullptr;
    cudaDriverEntryPointQueryResult qres;
    cudaGetDriverEntryPointByVersion("cuTensorMapEncodeTiled", (void**)&enc, 12000,
                                     cudaEnableDefault, &qres);
    if (!enc) return;   // no TMA encode available -> cannot run

    CUtensorMap tmXA, tmWqkv, tmAttnA, tmWo;
    encode_map(enc, &tmXA,    xr,    16384, 1024);
    encode_map(enc, &tmWqkv,  wqkvr, 3072,  1024);
    encode_map(enc, &tmAttnA, attn,  16384, 1024);
    encode_map(enc, &tmWo,    wor,   1024,  1024);

    cudaFuncSetAttribute(gemm_tma<false>, cudaFuncAttributeMaxDynamicSharedMemorySize, GEMM_SMEM);
    cudaFuncSetAttribute(gemm_tma<true >, cudaFuncAttributeMaxDynamicSharedMemorySize, GEMM_SMEM);

    const int M = 16384, K = 1024;

    // tf32 pre-rounding (HBM-streaming)
    round_tf32<<<4096, 256>>>(x,    xr,    (16384 * 1024) / 4);
    round_tf32<<<1536, 256>>>(Wqkv, wqkvr, (3072  * 1024) / 4);
    round_tf32<<<512,  256>>>(Wo,   wor,   (1024  * 1024) / 4);

    gemm_tma<false><<<dim3(3072 / BN, M / BM), 128, GEMM_SMEM>>>(tmXA,    tmWqkv, nullptr, qkv, 3072, K);
    attn_kernel<<<M, 128>>>(qkv, attn);
    gemm_tma<true ><<<dim3(1024 / BN, M / BM), 128, GEMM_SMEM>>>(tmAttnA, tmWo,   bo,      out, 1024, K);
}